// round 2
// baseline (speedup 1.0000x reference)
#include <cuda_runtime.h>
#include <cmath>

// ---------------- constants ----------------
#define LDP 68                      // padded pitch for 64x64 smem matrices (mm64 path)
#define MAT (64 * LDP)
#define NMAT 256
#define DSQ 4096
#define KSPLIT 32                   // gram k-split (chunks of 128)

// ---------------- device scratch (static: no allocation) ----------------
__device__ float g_logX[NMAT * DSQ];            // 4 MB
__device__ float g_B[NMAT * DSQ];               // 4 MB
__device__ float g_Gp[KSPLIT * NMAT * NMAT];    // 8 MB gram partials
__device__ float g_G[NMAT * NMAT];
__device__ float g_diag[NMAT];
__device__ float g_W[NMAT * NMAT];
__device__ float g_ssum[NMAT];
__device__ float g_rowsum[NMAT];
__device__ float g_colsum[NMAT];

__constant__ int c_TI[10] = {0, 0, 0, 0, 1, 1, 1, 2, 2, 3};
__constant__ int c_TJ[10] = {0, 1, 2, 3, 1, 2, 3, 2, 3, 3};

// ---------------- helpers ----------------
struct LogCoefs {
    float m[17];     // monomial coeffs of p(t) ~ log(x), t = scaleT*x - shiftT, deg 16
    float scaleT;
    float shiftT;
};

__device__ __forceinline__ float blockSum256(float v, float* red) {
    __syncthreads();
    int lane = threadIdx.x & 31, wid = threadIdx.x >> 5;
#pragma unroll
    for (int o = 16; o > 0; o >>= 1) v += __shfl_down_sync(0xffffffffu, v, o);
    if (lane == 0) red[wid] = v;
    __syncthreads();
    if (wid == 0) {
        v = (lane < 8) ? red[lane] : 0.f;
#pragma unroll
        for (int o = 4; o > 0; o >>= 1) v += __shfl_down_sync(0xffffffffu, v, o);
        if (lane == 0) red[0] = v;
    }
    __syncthreads();
    return red[0];
}

// C = A*B (64x64, pitch LDP). Alias-safe (sync before writes). Exits synced.
__device__ __forceinline__ void mm64(float* __restrict__ C, const float* A, const float* B, int tid) {
    const int r0 = (tid >> 4) << 2;
    const int c0 = (tid & 15) << 2;
    float4 acc0 = {0, 0, 0, 0}, acc1 = {0, 0, 0, 0}, acc2 = {0, 0, 0, 0}, acc3 = {0, 0, 0, 0};
    const float* Ar0 = A + (r0 + 0) * LDP;
    const float* Ar1 = A + (r0 + 1) * LDP;
    const float* Ar2 = A + (r0 + 2) * LDP;
    const float* Ar3 = A + (r0 + 3) * LDP;
#pragma unroll 8
    for (int k = 0; k < 64; k++) {
        float4 b = *(const float4*)(B + k * LDP + c0);
        float a0 = Ar0[k], a1 = Ar1[k], a2 = Ar2[k], a3 = Ar3[k];
        acc0.x += a0 * b.x; acc0.y += a0 * b.y; acc0.z += a0 * b.z; acc0.w += a0 * b.w;
        acc1.x += a1 * b.x; acc1.y += a1 * b.y; acc1.z += a1 * b.z; acc1.w += a1 * b.w;
        acc2.x += a2 * b.x; acc2.y += a2 * b.y; acc2.z += a2 * b.z; acc2.w += a2 * b.w;
        acc3.x += a3 * b.x; acc3.y += a3 * b.y; acc3.z += a3 * b.z; acc3.w += a3 * b.w;
    }
    __syncthreads();
    *(float4*)(C + (r0 + 0) * LDP + c0) = acc0;
    *(float4*)(C + (r0 + 1) * LDP + c0) = acc1;
    *(float4*)(C + (r0 + 2) * LDP + c0) = acc2;
    *(float4*)(C + (r0 + 3) * LDP + c0) = acc3;
    __syncthreads();
}

// ---------------- kernel 1: matrix log, Chebyshev deg 16, PS s=4 (6 matmuls) --------
extern "C" __global__ void __launch_bounds__(256) log_kernel(const float* __restrict__ X, LogCoefs cf) {
    extern __shared__ float sm[];
    float* P1 = sm;
    float* P2 = sm + MAT;
    float* P3 = sm + 2 * MAT;
    float* P4 = sm + 3 * MAT;
    float* R  = sm + 4 * MAT;
    __shared__ float red[32];

    const int tid = threadIdx.x;
    const int n = blockIdx.x;
    const float* Xn = X + n * DSQ;

    for (int idx = tid; idx < DSQ; idx += 256) {
        int r = idx >> 6, c = idx & 63;
        float v = Xn[idx] * cf.scaleT;
        if (r == c) v -= cf.shiftT;
        P1[r * LDP + c] = v;
    }
    __syncthreads();

    mm64(P2, P1, P1, tid);
    mm64(P3, P2, P1, tid);
    mm64(P4, P2, P2, tid);

    // init: R = m16*T4 + (m12 I + m13 T + m14 T2 + m15 T3)
    for (int idx = tid; idx < DSQ; idx += 256) {
        int r = idx >> 6, c = idx & 63;
        int o = r * LDP + c;
        float v = cf.m[16] * P4[o] + cf.m[13] * P1[o] + cf.m[14] * P2[o] + cf.m[15] * P3[o];
        if (r == c) v += cf.m[12];
        R[o] = v;
    }
    __syncthreads();

#pragma unroll
    for (int j = 2; j >= 0; j--) {
        mm64(R, R, P4, tid);   // in-place: R = R*T4
        float b0 = cf.m[4 * j], b1 = cf.m[4 * j + 1], b2 = cf.m[4 * j + 2], b3 = cf.m[4 * j + 3];
        for (int idx = tid; idx < DSQ; idx += 256) {
            int r = idx >> 6, c = idx & 63;
            int o = r * LDP + c;
            float v = b1 * P1[o] + b2 * P2[o] + b3 * P3[o];
            if (r == c) v += b0;
            R[o] += v;
        }
        __syncthreads();
    }

    float s = 0.f;
    for (int idx = tid; idx < DSQ; idx += 256) {
        int r = idx >> 6, c = idx & 63;
        float v = R[r * LDP + c];
        g_logX[n * DSQ + idx] = v;
        s += v;
    }
    float stot = blockSum256(s, red);
    if (tid == 0) g_ssum[n] = stot;
}

// ---------------- kernel 2: Gram partials, triangular tiles, 4x4 blocking ----------
// XOR-swizzled 64x64 tiles: row-float4 loads hit the 2-phase crossbar optimum.
__device__ __forceinline__ int gsw(int row, int col) {
    return row * 64 + (col ^ ((row & 15) << 2));
}

extern "C" __global__ void __launch_bounds__(256) gram_kernel() {
    __shared__ float sA[4096];
    __shared__ float sB[4096];
    const int tid = threadIdx.x;
    const int kc = blockIdx.x;           // 0..31, k-chunk of 128
    const int pr = blockIdx.y;           // 0..9 triangular tile pair
    const int ti = c_TI[pr], tj = c_TJ[pr];
    const int i0 = ti * 64, j0 = tj * 64;
    const int kb = kc * 128;
    const int r1 = tid >> 4, c1 = tid & 15;

    float acc[4][4] = {};
    for (int ks = 0; ks < 128; ks += 64) {
        for (int q = tid; q < 1024; q += 256) {
            int row = q >> 4, col4 = (q & 15) << 2;
            *(float4*)&sA[gsw(row, col4)] = *(const float4*)&g_logX[(i0 + row) * DSQ + kb + ks + col4];
            *(float4*)&sB[gsw(row, col4)] = *(const float4*)&g_logX[(j0 + row) * DSQ + kb + ks + col4];
        }
        __syncthreads();
#pragma unroll 4
        for (int k4 = 0; k4 < 64; k4 += 4) {
            float4 a[4], b[4];
#pragma unroll
            for (int u = 0; u < 4; u++) {
                a[u] = *(const float4*)&sA[gsw(r1 + 16 * u, k4)];
                b[u] = *(const float4*)&sB[gsw(c1 + 16 * u, k4)];
            }
#pragma unroll
            for (int ii = 0; ii < 4; ii++)
#pragma unroll
                for (int jj = 0; jj < 4; jj++)
                    acc[ii][jj] += a[ii].x * b[jj].x + a[ii].y * b[jj].y
                                 + a[ii].z * b[jj].z + a[ii].w * b[jj].w;
        }
        __syncthreads();
    }
    float* P = g_Gp + kc * (NMAT * NMAT);
#pragma unroll
    for (int ii = 0; ii < 4; ii++)
#pragma unroll
        for (int jj = 0; jj < 4; jj++) {
            int gi = i0 + r1 + 16 * ii, gj = j0 + c1 + 16 * jj;
            P[gi * NMAT + gj] = acc[ii][jj];
            if (ti != tj) P[gj * NMAT + gi] = acc[ii][jj];
        }
}

// ---------------- kernel 2b: reduce gram partials, extract diag, zero colsum -------
extern "C" __global__ void __launch_bounds__(256) gred_kernel() {
    const int r = blockIdx.x, c = threadIdx.x;
    float s = 0.f;
#pragma unroll 8
    for (int kc = 0; kc < KSPLIT; kc++) s += g_Gp[kc * (NMAT * NMAT) + r * NMAT + c];
    g_G[r * NMAT + c] = s;
    if (c == r) g_diag[r] = s;
    if (r == 0) g_colsum[c] = 0.f;
}

// ---------------- kernel 3: weights W + row sums + column sums (atomic) ------------
extern "C" __global__ void __launch_bounds__(256) weight_kernel(const float* __restrict__ bwp) {
    __shared__ float red[32];
    const int i = blockIdx.x, j = threadIdx.x;
    const float bw = bwp[0];
    const float eps = 1e-7f;
    float Gii = g_diag[i];
    float Gjj = g_diag[j];
    float Gij = g_G[i * NMAT + j];
    float si = g_ssum[i], sj = g_ssum[j];
    float pds = Gii + Gjj - 2.f * Gij + 2.f * eps * (sj - si) + eps * eps * 4096.f;
    float w = expf(-0.5f * pds / (bw * bw));
    g_W[i * NMAT + j] = w;
    atomicAdd(&g_colsum[j], w);
    float rs = blockSum256(w, red);
    if (j == 0) g_rowsum[i] = rs;
}

// ---------------- kernel 4: B = (1 - colsum/rowsum)*L[k] + (W^T L)[k]/rowsum -------
extern "C" __global__ void __launch_bounds__(256) shift_kernel() {
    __shared__ float sW[64 * LDP];  // W[j][k] chunk
    __shared__ float sL[64 * LDP];  // L[j][e] chunk
    const int tid = threadIdx.x;
    const int e0 = blockIdx.x * 64, k0 = blockIdx.y * 64;
    const int r0 = (tid >> 4) << 2;   // k-dim
    const int c0 = (tid & 15) << 2;   // e-dim

    float4 acc0 = {0, 0, 0, 0}, acc1 = {0, 0, 0, 0}, acc2 = {0, 0, 0, 0}, acc3 = {0, 0, 0, 0};
    for (int jc = 0; jc < NMAT; jc += 64) {
        for (int q = tid; q < 64 * 16; q += 256) {
            int jj = q >> 4, cc = (q & 15) << 2;
            *(float4*)&sW[jj * LDP + cc] = *(const float4*)&g_W[(jc + jj) * NMAT + k0 + cc];
            *(float4*)&sL[jj * LDP + cc] = *(const float4*)&g_logX[(jc + jj) * DSQ + e0 + cc];
        }
        __syncthreads();
#pragma unroll 4
        for (int jj = 0; jj < 64; jj++) {
            float a0 = sW[jj * LDP + r0 + 0];
            float a1 = sW[jj * LDP + r0 + 1];
            float a2 = sW[jj * LDP + r0 + 2];
            float a3 = sW[jj * LDP + r0 + 3];
            float4 b = *(const float4*)&sL[jj * LDP + c0];
            acc0.x += a0 * b.x; acc0.y += a0 * b.y; acc0.z += a0 * b.z; acc0.w += a0 * b.w;
            acc1.x += a1 * b.x; acc1.y += a1 * b.y; acc1.z += a1 * b.z; acc1.w += a1 * b.w;
            acc2.x += a2 * b.x; acc2.y += a2 * b.y; acc2.z += a2 * b.z; acc2.w += a2 * b.w;
            acc3.x += a3 * b.x; acc3.y += a3 * b.y; acc3.z += a3 * b.z; acc3.w += a3 * b.w;
        }
        __syncthreads();
    }
    float4 accs[4] = {acc0, acc1, acc2, acc3};
#pragma unroll
    for (int i = 0; i < 4; i++) {
        int k = k0 + r0 + i;
        float rs = g_rowsum[k];
        float ir = 1.f / rs;
        float al = 1.f - g_colsum[k] * ir;
        float4 Lv = *(const float4*)&g_logX[k * DSQ + e0 + c0];
        float4 o;
        o.x = accs[i].x * ir + al * Lv.x;
        o.y = accs[i].y * ir + al * Lv.y;
        o.z = accs[i].z * ir + al * Lv.z;
        o.w = accs[i].w * ir + al * Lv.w;
        *(float4*)&g_B[k * DSQ + e0 + c0] = o;
    }
}

// ---------------- kernel 5: matrix exp, Taylor 12 / PS s=4, thresh 2.0 -------------
extern "C" __global__ void __launch_bounds__(256) exp_kernel(float* __restrict__ out) {
    extern __shared__ float sm[];
    float* S  = sm;
    float* S2 = sm + MAT;
    float* S3 = sm + 2 * MAT;
    float* S4 = sm + 3 * MAT;
    float* R  = sm + 4 * MAT;
    __shared__ float red[32];

    const int tid = threadIdx.x;
    const int n = blockIdx.x;

    float ss = 0.f;
    for (int idx = tid; idx < DSQ; idx += 256) {
        int r = idx >> 6, c = idx & 63;
        float v = g_B[n * DSQ + idx];
        S[r * LDP + c] = v;
        ss += v * v;
    }
    float theta = sqrtf(blockSum256(ss, red));
    int kk = 0;
    float t = theta;
    while (t > 2.0f && kk < 10) { t *= 0.5f; kk++; }
    float sc = ldexpf(1.f, -kk);
    for (int idx = tid; idx < DSQ; idx += 256) {
        int r = idx >> 6, c = idx & 63;
        S[r * LDP + c] *= sc;
    }
    __syncthreads();

    mm64(S2, S, S, tid);
    mm64(S3, S2, S, tid);
    mm64(S4, S2, S2, tid);

    const float c0 = 1.f, c1 = 1.f, c2 = 0.5f, c3 = 1.f / 6.f, c4 = 1.f / 24.f, c5 = 1.f / 120.f,
                c6 = 1.f / 720.f, c7 = 1.f / 5040.f, c8 = 1.f / 40320.f, c9 = 1.f / 362880.f,
                c10 = 1.f / 3628800.f, c11 = 1.f / 39916800.f, c12 = 1.f / 479001600.f;
    const float gI[3]  = {c0, c4, c8};
    const float gS[3]  = {c1, c5, c9};
    const float gS2[3] = {c2, c6, c10};
    const float gS3[3] = {c3, c7, c11};

    // init: R = c12*S4 + (c8 I + c9 S + c10 S2 + c11 S3)
    for (int idx = tid; idx < DSQ; idx += 256) {
        int r = idx >> 6, c = idx & 63;
        int o = r * LDP + c;
        float v = c12 * S4[o] + gS[2] * S[o] + gS2[2] * S2[o] + gS3[2] * S3[o];
        if (r == c) v += gI[2];
        R[o] = v;
    }
    __syncthreads();
#pragma unroll
    for (int j = 1; j >= 0; j--) {
        mm64(R, R, S4, tid);
        float aI = gI[j], aS = gS[j], aS2 = gS2[j], aS3 = gS3[j];
        for (int idx = tid; idx < DSQ; idx += 256) {
            int r = idx >> 6, c = idx & 63;
            int o = r * LDP + c;
            float v = aS * S[o] + aS2 * S2[o] + aS3 * S3[o];
            if (r == c) v += aI;
            R[o] += v;
        }
        __syncthreads();
    }
    for (int q = 0; q < kk; q++) mm64(R, R, R, tid);  // squarings

    for (int idx = tid; idx < DSQ; idx += 256) {
        int r = idx >> 6, c = idx & 63;
        out[n * DSQ + idx] = R[r * LDP + c];
    }
}

// ---------------- host: log coefficients (closed-form Chebyshev -> monomial) -------
static LogCoefs make_log_coefs() {
    const double a = 0.48, b = 6.5;
    const double c = 0.5 * (a + b);
    const double beta = (b - a) / (b + a);
    const double z = (std::sqrt(1.0 - beta * beta) - 1.0) / beta;  // negative, |z|<1
    const int DEG = 16;
    double cheb[DEG + 1];
    cheb[0] = std::log(c) - std::log(1.0 + z * z);
    double zk = 1.0;
    for (int k = 1; k <= DEG; k++) { zk *= z; cheb[k] = -2.0 * zk / (double)k; }

    double m[DEG + 1] = {0};
    double Tprev[DEG + 1] = {0}, Tcur[DEG + 1] = {0}, Tnext[DEG + 1];
    Tprev[0] = 1.0;
    m[0] += cheb[0];
    Tcur[1] = 1.0;
    m[1] += cheb[1];
    for (int k = 2; k <= DEG; k++) {
        for (int j = 0; j <= DEG; j++) Tnext[j] = -Tprev[j];
        for (int j = 0; j < DEG; j++) Tnext[j + 1] += 2.0 * Tcur[j];
        for (int j = 0; j <= k; j++) m[j] += cheb[k] * Tnext[j];
        for (int j = 0; j <= DEG; j++) { Tprev[j] = Tcur[j]; Tcur[j] = Tnext[j]; }
    }
    LogCoefs cf;
    for (int j = 0; j <= DEG; j++) cf.m[j] = (float)m[j];
    cf.scaleT = (float)(2.0 / (b - a));
    cf.shiftT = (float)((a + b) / (b - a));
    return cf;
}

// ---------------- entry point ----------------
extern "C" void kernel_launch(void* const* d_in, const int* in_sizes, int n_in,
                              void* d_out, int out_size) {
    const float* X  = (const float*)d_in[0];   // [256,64,64] fp32
    const float* bw = (const float*)d_in[1];   // scalar fp32
    float* out = (float*)d_out;                // [256,64,64] fp32

    const int SMEM5 = 5 * MAT * (int)sizeof(float);  // 87040 B
    cudaFuncSetAttribute(log_kernel, cudaFuncAttributeMaxDynamicSharedMemorySize, SMEM5);
    cudaFuncSetAttribute(exp_kernel, cudaFuncAttributeMaxDynamicSharedMemorySize, SMEM5);

    LogCoefs cf = make_log_coefs();

    log_kernel<<<NMAT, 256, SMEM5>>>(X, cf);
    gram_kernel<<<dim3(KSPLIT, 10), 256>>>();
    gred_kernel<<<NMAT, 256>>>();
    weight_kernel<<<NMAT, 256>>>(bw);
    shift_kernel<<<dim3(64, 4), 256>>>();
    exp_kernel<<<NMAT, 256, SMEM5>>>(out);
}

// round 4
// speedup vs baseline: 1.6374x; 1.6374x over previous
#include <cuda_runtime.h>
#include <cmath>

// ---------------- constants ----------------
#define NMAT 256
#define DSQ 4096
#define KSPLIT 32                   // gram k-split (chunks of 128)

typedef unsigned long long u64;

// ---------------- device scratch (static: no allocation) ----------------
__device__ float g_logX[NMAT * DSQ];            // 4 MB
__device__ float g_B[NMAT * DSQ];               // 4 MB
__device__ float g_Gp[KSPLIT * NMAT * NMAT];    // 8 MB gram partials
__device__ float g_W[NMAT * NMAT];
__device__ float g_ssum[NMAT];
__device__ float g_sq[NMAT];
__device__ float g_rowsum[NMAT];
__device__ float g_colsum[NMAT];

__constant__ int c_TI[10] = {0, 0, 0, 0, 1, 1, 1, 2, 2, 3};
__constant__ int c_TJ[10] = {0, 1, 2, 3, 1, 2, 3, 2, 3, 3};

// ---------------- f32x2 packed-FMA helpers ----------------
__device__ __forceinline__ u64 pack2(float a) {
    u64 r;
    asm("mov.b64 %0, {%1, %1};" : "=l"(r) : "f"(a));
    return r;
}
__device__ __forceinline__ void fma2(u64& acc, u64 a, u64 b) {
    asm("fma.rn.f32x2 %0, %1, %2, %0;" : "+l"(acc) : "l"(a), "l"(b));
}
__device__ __forceinline__ float2 unpack2(u64 v) {
    float2 r;
    asm("mov.b64 {%0, %1}, %2;" : "=f"(r.x), "=f"(r.y) : "l"(v));
    return r;
}

// ---------------- misc helpers ----------------
struct LogCoefs {
    float m[16];     // monomial coeffs of p(t) ~ log(x), t = scaleT*x - shiftT, deg 15
    float scaleT;
    float shiftT;
};

__device__ __forceinline__ float blockSum256(float v, float* red) {
    __syncthreads();
    int lane = threadIdx.x & 31, wid = threadIdx.x >> 5;
#pragma unroll
    for (int o = 16; o > 0; o >>= 1) v += __shfl_down_sync(0xffffffffu, v, o);
    if (lane == 0) red[wid] = v;
    __syncthreads();
    if (wid == 0) {
        v = (lane < 8) ? red[lane] : 0.f;
#pragma unroll
        for (int o = 4; o > 0; o >>= 1) v += __shfl_down_sync(0xffffffffu, v, o);
        if (lane == 0) red[0] = v;
    }
    __syncthreads();
    return red[0];
}

// C = A*B (64x64, pitch 64) with packed f32x2 FMAs. Alias-safe. Exits synced.
__device__ __forceinline__ void mm64(float* C, const float* A, const float* B, int tid) {
    const int r0 = (tid >> 4) << 2;
    const int c0 = (tid & 15) << 2;
    u64 acc[4][2] = {};
#pragma unroll 2
    for (int k4 = 0; k4 < 64; k4 += 4) {
        float4 av[4];
#pragma unroll
        for (int i = 0; i < 4; i++) av[i] = *(const float4*)(A + (r0 + i) * 64 + k4);
#pragma unroll
        for (int kk = 0; kk < 4; kk++) {
            ulonglong2 b = *(const ulonglong2*)(B + (k4 + kk) * 64 + c0);
#pragma unroll
            for (int i = 0; i < 4; i++) {
                float a = (kk == 0) ? av[i].x : (kk == 1) ? av[i].y : (kk == 2) ? av[i].z : av[i].w;
                u64 pa = pack2(a);
                fma2(acc[i][0], pa, b.x);
                fma2(acc[i][1], pa, b.y);
            }
        }
    }
    __syncthreads();
#pragma unroll
    for (int i = 0; i < 4; i++) {
        float2 lo = unpack2(acc[i][0]);
        float2 hi = unpack2(acc[i][1]);
        float4 o = make_float4(lo.x, lo.y, hi.x, hi.y);
        *(float4*)(C + (r0 + i) * 64 + c0) = o;
    }
    __syncthreads();
}

// ---------------- kernel 1: matrix log, Chebyshev deg 15, PS s=3 (6 matmuls) --------
extern "C" __global__ void __launch_bounds__(256) log_kernel(const float* __restrict__ X, LogCoefs cf) {
    extern __shared__ float sm[];
    float* P1 = sm;              // T
    float* P2 = sm + DSQ;        // T^2
    float* P3 = sm + 2 * DSQ;    // T^3
    float* R  = sm + 3 * DSQ;
    __shared__ float red[32];

    const int tid = threadIdx.x;
    const int n = blockIdx.x;
    const float* Xn = X + n * DSQ;

    if (tid == 0) g_colsum[n] = 0.f;   // pre-zero for weight_kernel's atomics

    for (int idx = tid; idx < DSQ; idx += 256) {
        int r = idx >> 6, c = idx & 63;
        float v = Xn[idx] * cf.scaleT;
        if (r == c) v -= cf.shiftT;
        P1[idx] = v;
    }
    __syncthreads();

    mm64(P2, P1, P1, tid);
    mm64(P3, P2, P1, tid);

    // init: R = m15*T3 + (m12 I + m13 T + m14 T2)
    for (int idx = tid; idx < DSQ; idx += 256) {
        int r = idx >> 6, c = idx & 63;
        float v = cf.m[15] * P3[idx] + cf.m[13] * P1[idx] + cf.m[14] * P2[idx];
        if (r == c) v += cf.m[12];
        R[idx] = v;
    }
    __syncthreads();

#pragma unroll
    for (int j = 3; j >= 0; j--) {
        mm64(R, R, P3, tid);   // in-place: R = R*T3
        float b0 = cf.m[3 * j], b1 = cf.m[3 * j + 1], b2 = cf.m[3 * j + 2];
        for (int idx = tid; idx < DSQ; idx += 256) {
            int r = idx >> 6, c = idx & 63;
            float v = b1 * P1[idx] + b2 * P2[idx];
            if (r == c) v += b0;
            R[idx] += v;
        }
        __syncthreads();
    }

    float s = 0.f, q = 0.f;
    for (int idx = tid; idx < DSQ; idx += 256) {
        float v = R[idx];
        g_logX[n * DSQ + idx] = v;
        s += v;
        q += v * v;
    }
    float stot = blockSum256(s, red);
    float qtot = blockSum256(q, red);
    if (tid == 0) { g_ssum[n] = stot; g_sq[n] = qtot; }
}

// ---------------- kernel 2: Gram partials, triangular tiles, 4x4 blocking ----------
__device__ __forceinline__ int gsw(int row, int col) {
    return row * 64 + (col ^ ((row & 15) << 2));
}

extern "C" __global__ void __launch_bounds__(256) gram_kernel() {
    __shared__ float sA[4096];
    __shared__ float sB[4096];
    const int tid = threadIdx.x;
    const int kc = blockIdx.x;           // 0..31, k-chunk of 128
    const int pr = blockIdx.y;           // 0..9 triangular tile pair
    const int ti = c_TI[pr], tj = c_TJ[pr];
    const int i0 = ti * 64, j0 = tj * 64;
    const int kb = kc * 128;
    const int r1 = tid >> 4, c1 = tid & 15;

    u64 acc[4][4] = {};
    for (int ks = 0; ks < 128; ks += 64) {
        for (int q = tid; q < 1024; q += 256) {
            int row = q >> 4, col4 = (q & 15) << 2;
            *(float4*)&sA[gsw(row, col4)] = *(const float4*)&g_logX[(i0 + row) * DSQ + kb + ks + col4];
            *(float4*)&sB[gsw(row, col4)] = *(const float4*)&g_logX[(j0 + row) * DSQ + kb + ks + col4];
        }
        __syncthreads();
#pragma unroll 2
        for (int k4 = 0; k4 < 64; k4 += 4) {
            ulonglong2 a2[4], b2[4];
#pragma unroll
            for (int u = 0; u < 4; u++) {
                a2[u] = *(const ulonglong2*)&sA[gsw(r1 + 16 * u, k4)];
                b2[u] = *(const ulonglong2*)&sB[gsw(c1 + 16 * u, k4)];
            }
#pragma unroll
            for (int ii = 0; ii < 4; ii++)
#pragma unroll
                for (int jj = 0; jj < 4; jj++) {
                    fma2(acc[ii][jj], a2[ii].x, b2[jj].x);
                    fma2(acc[ii][jj], a2[ii].y, b2[jj].y);
                }
        }
        __syncthreads();
    }
    float* P = g_Gp + kc * (NMAT * NMAT);
#pragma unroll
    for (int ii = 0; ii < 4; ii++)
#pragma unroll
        for (int jj = 0; jj < 4; jj++) {
            float2 p = unpack2(acc[ii][jj]);
            float v = p.x + p.y;
            int gi = i0 + r1 + 16 * ii, gj = j0 + c1 + 16 * jj;
            P[gi * NMAT + gj] = v;
            if (ti != tj) P[gj * NMAT + gi] = v;
        }
}

// ---------------- kernel 3: reduce partials + weights + row/col sums ---------------
extern "C" __global__ void __launch_bounds__(256) weight_kernel(const float* __restrict__ bwp) {
    __shared__ float red[32];
    const int i = blockIdx.x, j = threadIdx.x;
    const float bw = bwp[0];
    const float eps = 1e-7f;

    float g = 0.f;
#pragma unroll 8
    for (int kc = 0; kc < KSPLIT; kc++) g += g_Gp[kc * (NMAT * NMAT) + i * NMAT + j];

    float pds = g_sq[i] + g_sq[j] - 2.f * g
              + 2.f * eps * (g_ssum[j] - g_ssum[i]) + eps * eps * 4096.f;
    float w = expf(-0.5f * pds / (bw * bw));
    g_W[i * NMAT + j] = w;
    atomicAdd(&g_colsum[j], w);
    float rs = blockSum256(w, red);
    if (j == 0) g_rowsum[i] = rs;
}

// ---------------- kernel 4: B = (1 - colsum/rowsum)*L[k] + (W^T L)[k]/rowsum -------
extern "C" __global__ void __launch_bounds__(256) shift_kernel() {
    __shared__ float sW[4096];  // W[j][k] chunk (64x64)
    __shared__ float sL[4096];  // L[j][e] chunk (64x64)
    const int tid = threadIdx.x;
    const int e0 = blockIdx.x * 64, k0 = blockIdx.y * 64;
    const int r0 = (tid >> 4) << 2;   // k-dim
    const int c0 = (tid & 15) << 2;   // e-dim

    u64 acc[4][2] = {};
    for (int jc = 0; jc < NMAT; jc += 64) {
        for (int q = tid; q < 1024; q += 256) {
            int jj = q >> 4, cc = (q & 15) << 2;
            *(float4*)&sW[jj * 64 + cc] = *(const float4*)&g_W[(jc + jj) * NMAT + k0 + cc];
            *(float4*)&sL[jj * 64 + cc] = *(const float4*)&g_logX[(jc + jj) * DSQ + e0 + cc];
        }
        __syncthreads();
#pragma unroll 4
        for (int jj = 0; jj < 64; jj++) {
            ulonglong2 b = *(const ulonglong2*)&sL[jj * 64 + c0];
#pragma unroll
            for (int i = 0; i < 4; i++) {
                u64 pa = pack2(sW[jj * 64 + r0 + i]);
                fma2(acc[i][0], pa, b.x);
                fma2(acc[i][1], pa, b.y);
            }
        }
        __syncthreads();
    }
#pragma unroll
    for (int i = 0; i < 4; i++) {
        int k = k0 + r0 + i;
        float rs = g_rowsum[k];
        float ir = 1.f / rs;
        float al = 1.f - g_colsum[k] * ir;
        float2 lo = unpack2(acc[i][0]);
        float2 hi = unpack2(acc[i][1]);
        float4 Lv = *(const float4*)&g_logX[k * DSQ + e0 + c0];
        float4 o;
        o.x = lo.x * ir + al * Lv.x;
        o.y = lo.y * ir + al * Lv.y;
        o.z = hi.x * ir + al * Lv.z;
        o.w = hi.y * ir + al * Lv.w;
        *(float4*)&g_B[k * DSQ + e0 + c0] = o;
    }
}

// ---------------- kernel 5: matrix exp, Taylor 12 / PS s=3 (5 mm + squarings) ------
extern "C" __global__ void __launch_bounds__(256) exp_kernel(float* __restrict__ out) {
    extern __shared__ float sm[];
    float* S  = sm;
    float* S2 = sm + DSQ;
    float* S3 = sm + 2 * DSQ;
    float* R  = sm + 3 * DSQ;
    __shared__ float red[32];

    const int tid = threadIdx.x;
    const int n = blockIdx.x;

    float ss = 0.f;
    for (int idx = tid; idx < DSQ; idx += 256) {
        float v = g_B[n * DSQ + idx];
        S[idx] = v;
        ss += v * v;
    }
    float theta = sqrtf(blockSum256(ss, red));
    int kk = 0;
    float t = theta;
    while (t > 2.0f && kk < 8) { t *= 0.5f; kk++; }
    float sc = ldexpf(1.f, -kk);
    for (int idx = tid; idx < DSQ; idx += 256) S[idx] *= sc;
    __syncthreads();

    mm64(S2, S, S, tid);
    mm64(S3, S2, S, tid);

    const float c0 = 1.f, c1 = 1.f, c2 = 0.5f, c3 = 1.f / 6.f, c4 = 1.f / 24.f, c5 = 1.f / 120.f,
                c6 = 1.f / 720.f, c7 = 1.f / 5040.f, c8 = 1.f / 40320.f, c9 = 1.f / 362880.f,
                c10 = 1.f / 3628800.f, c11 = 1.f / 39916800.f, c12 = 1.f / 479001600.f;
    const float gI[3]  = {c0, c3, c6};
    const float gS[3]  = {c1, c4, c7};
    const float gS2[3] = {c2, c5, c8};

    // init: R = c12*S3 + (c9 I + c10 S + c11 S2)
    for (int idx = tid; idx < DSQ; idx += 256) {
        int r = idx >> 6, c = idx & 63;
        float v = c12 * S3[idx] + c10 * S[idx] + c11 * S2[idx];
        if (r == c) v += c9;
        R[idx] = v;
    }
    __syncthreads();
#pragma unroll
    for (int j = 2; j >= 0; j--) {
        mm64(R, R, S3, tid);
        float aI = gI[j], aS = gS[j], aS2 = gS2[j];
        for (int idx = tid; idx < DSQ; idx += 256) {
            int r = idx >> 6, c = idx & 63;
            float v = aS * S[idx] + aS2 * S2[idx];
            if (r == c) v += aI;
            R[idx] += v;
        }
        __syncthreads();
    }
    for (int q = 0; q < kk; q++) mm64(R, R, R, tid);  // squarings

    for (int idx = tid; idx < DSQ; idx += 256) out[n * DSQ + idx] = R[idx];
}

// ---------------- host: log coefficients (closed-form Chebyshev -> monomial) -------
static LogCoefs make_log_coefs() {
    const double a = 0.48, b = 6.5;
    const double c = 0.5 * (a + b);
    const double beta = (b - a) / (b + a);
    const double z = (std::sqrt(1.0 - beta * beta) - 1.0) / beta;  // negative, |z|<1
    const int DEG = 15;
    double cheb[DEG + 1];
    cheb[0] = std::log(c) - std::log(1.0 + z * z);
    double zk = 1.0;
    for (int k = 1; k <= DEG; k++) { zk *= z; cheb[k] = -2.0 * zk / (double)k; }

    double m[DEG + 1] = {0};
    double Tprev[DEG + 1] = {0}, Tcur[DEG + 1] = {0}, Tnext[DEG + 1];
    Tprev[0] = 1.0;
    m[0] += cheb[0];
    Tcur[1] = 1.0;
    m[1] += cheb[1];
    for (int k = 2; k <= DEG; k++) {
        for (int j = 0; j <= DEG; j++) Tnext[j] = -Tprev[j];
        for (int j = 0; j < DEG; j++) Tnext[j + 1] += 2.0 * Tcur[j];
        for (int j = 0; j <= k; j++) m[j] += cheb[k] * Tnext[j];
        for (int j = 0; j <= DEG; j++) { Tprev[j] = Tcur[j]; Tcur[j] = Tnext[j]; }
    }
    LogCoefs cf;
    for (int j = 0; j <= DEG; j++) cf.m[j] = (float)m[j];
    cf.scaleT = (float)(2.0 / (b - a));
    cf.shiftT = (float)((a + b) / (b - a));
    return cf;
}

// ---------------- entry point ----------------
extern "C" void kernel_launch(void* const* d_in, const int* in_sizes, int n_in,
                              void* d_out, int out_size) {
    const float* X  = (const float*)d_in[0];   // [256,64,64] fp32
    const float* bw = (const float*)d_in[1];   // scalar fp32
    float* out = (float*)d_out;                // [256,64,64] fp32

    const int SMEM4 = 4 * DSQ * (int)sizeof(float);  // 65536 B -> 3 CTAs/SM
    cudaFuncSetAttribute(log_kernel, cudaFuncAttributeMaxDynamicSharedMemorySize, SMEM4);
    cudaFuncSetAttribute(exp_kernel, cudaFuncAttributeMaxDynamicSharedMemorySize, SMEM4);

    LogCoefs cf = make_log_coefs();

    log_kernel<<<NMAT, 256, SMEM4>>>(X, cf);
    gram_kernel<<<dim3(KSPLIT, 10), 256>>>();
    weight_kernel<<<NMAT, 256>>>(bw);
    shift_kernel<<<dim3(64, 4), 256>>>();
    exp_kernel<<<NMAT, 256, SMEM4>>>(out);
}